// round 9
// baseline (speedup 1.0000x reference)
#include <cuda_runtime.h>
#include <math.h>

#define T_LEN 2048
#define B_SZ  64
#define I_SZ  256
#define H_SZ  256

#define NGRP 16
#define CPG  8     // CTAs per group = cluster size
#define NB   4     // batches per group (2 phases x 2 batches)

typedef unsigned long long u64;

__device__ __forceinline__ void fma2(u64 &d, u64 a, u64 b) {
    asm("fma.rn.f32x2 %0, %1, %2, %0;" : "+l"(d) : "l"(a), "l"(b));
}
__device__ __forceinline__ float2 u2f(u64 v) {
    float2 r; asm("mov.b64 {%0, %1}, %2;" : "=f"(r.x), "=f"(r.y) : "l"(v)); return r;
}
__device__ __forceinline__ u64 dup2(float x) {
    u64 r; asm("mov.b64 %0, {%1, %1};" : "=l"(r) : "f"(x)); return r;
}
__device__ __forceinline__ unsigned smem_u32(const void* p) {
    unsigned a;
    asm("{ .reg .u64 t; cvta.to.shared.u64 t, %1; cvt.u32.u64 %0, t; }" : "=r"(a) : "l"(p));
    return a;
}

// ---------------- scratch ----------------------------------------------------
__device__ float g_xfh[(size_t)T_LEN * B_SZ * 512];   // [t][b][0:256]=xf, [256:512]=xh

// ---------------- projection GEMM (double-buffered, f32x2) -------------------
__global__ __launch_bounds__(256) void proj_kernel(
    const float* __restrict__ seq,
    const float* __restrict__ Wf, const float* __restrict__ bf,
    const float* __restrict__ Wh, const float* __restrict__ bh)
{
    __shared__ float2 As2[2][8][130];
    __shared__ float  Bs[2][8][132];

    const int bm = blockIdx.x;
    const int bn = blockIdx.y;
    const float* __restrict__ W    = (bn < 2) ? Wf : Wh;
    const float* __restrict__ bias = (bn < 2) ? bf : bh;
    const int nb = (bn & 1) * 128;

    const int tid  = threadIdx.x;
    const int tx   = tid & 15;
    const int ty   = tid >> 4;
    const int arow = tid >> 1, acol = (tid & 1) * 4;
    const int brow = tid >> 5, bcol = (tid & 31) * 4;
    const size_t abase = (size_t)(bm * 128 + arow) * 256 + acol;

    u64 acc[8][4];
#pragma unroll
    for (int i = 0; i < 8; i++)
#pragma unroll
        for (int j = 0; j < 4; j++) acc[i][j] = 0ull;

    {
        float4 av = *(const float4*)&seq[abase];
        float4 bv = *(const float4*)&W[(size_t)brow * 256 + nb + bcol];
        As2[0][acol + 0][arow] = make_float2(av.x, av.x);
        As2[0][acol + 1][arow] = make_float2(av.y, av.y);
        As2[0][acol + 2][arow] = make_float2(av.z, av.z);
        As2[0][acol + 3][arow] = make_float2(av.w, av.w);
        *(float4*)&Bs[0][brow][bcol] = bv;
    }
    __syncthreads();

    for (int it = 0; it < 32; it++) {
        const int p = it & 1;
        float4 av, bv;
        if (it < 31) {
            const int k0 = (it + 1) * 8;
            av = *(const float4*)&seq[abase + k0];
            bv = *(const float4*)&W[(size_t)(k0 + brow) * 256 + nb + bcol];
        }
#pragma unroll
        for (int k = 0; k < 8; k++) {
            ulonglong2 a01 = *(const ulonglong2*)&As2[p][k][ty * 8 + 0];
            ulonglong2 a23 = *(const ulonglong2*)&As2[p][k][ty * 8 + 2];
            ulonglong2 a45 = *(const ulonglong2*)&As2[p][k][ty * 8 + 4];
            ulonglong2 a67 = *(const ulonglong2*)&As2[p][k][ty * 8 + 6];
            ulonglong2 b01 = *(const ulonglong2*)&Bs[p][k][tx * 8];
            ulonglong2 b23 = *(const ulonglong2*)&Bs[p][k][tx * 8 + 4];
            u64 ad[8] = {a01.x, a01.y, a23.x, a23.y, a45.x, a45.y, a67.x, a67.y};
#pragma unroll
            for (int i = 0; i < 8; i++) {
                fma2(acc[i][0], ad[i], b01.x);
                fma2(acc[i][1], ad[i], b01.y);
                fma2(acc[i][2], ad[i], b23.x);
                fma2(acc[i][3], ad[i], b23.y);
            }
        }
        if (it < 31) {
            const int np = p ^ 1;
            As2[np][acol + 0][arow] = make_float2(av.x, av.x);
            As2[np][acol + 1][arow] = make_float2(av.y, av.y);
            As2[np][acol + 2][arow] = make_float2(av.z, av.z);
            As2[np][acol + 3][arow] = make_float2(av.w, av.w);
            *(float4*)&Bs[np][brow][bcol] = bv;
        }
        __syncthreads();
    }

    float bb[8];
#pragma unroll
    for (int j = 0; j < 8; j++) bb[j] = bias[nb + tx * 8 + j];

#pragma unroll
    for (int i = 0; i < 8; i++) {
        size_t m = (size_t)bm * 128 + ty * 8 + i;
        float* op = &g_xfh[m * 512 + (size_t)bn * 128 + tx * 8];
        float2 c0 = u2f(acc[i][0]), c1 = u2f(acc[i][1]);
        float2 c2 = u2f(acc[i][2]), c3 = u2f(acc[i][3]);
        float4 v0, v1;
        v0.x = c0.x + bb[0]; v0.y = c0.y + bb[1];
        v0.z = c1.x + bb[2]; v0.w = c1.y + bb[3];
        v1.x = c2.x + bb[4]; v1.y = c2.y + bb[5];
        v1.z = c3.x + bb[6]; v1.w = c3.y + bb[7];
        *(float4*)&op[0] = v0;
        *(float4*)&op[4] = v1;
    }
}

// ---------------- persistent recurrence: batch-phase pipelined exchange -----
// Step split into 2 phases (batches {0,1} then {2,3}). Phase p of step t+1
// depends only on phase-p sends of step t, issued one full phase earlier, so
// DSMEM flight hides behind the opposite phase's compute + epilogue.
// Barriers: mbar[buf][phase], expect 8 x 256 B. Same expect-before-send chain.
__global__ __launch_bounds__(256, 1) __cluster_dims__(CPG, 1, 1)
void rec_kernel(const float* __restrict__ Uf, const float* __restrict__ Uh,
                const float* __restrict__ pa, float* __restrict__ out)
{
    __shared__ float2 sHp[2][2][256];                  // 8 KB recv: [buf][ph][k]=(hA,hB)
    __shared__ float  sRed[64 * 17];                   // 4.4 KB: [vc][bb*8+w]
    __shared__ __align__(16) float sOut[2][2][64];     // 1 KB staging: [buf][ph][col*2+bb]
    __shared__ __align__(16) u64 mbar[4];              // [buf*2+phase]

    const int g   = blockIdx.x >> 3;
    unsigned cgi;
    asm("mov.u32 %0, %%cluster_ctarank;" : "=r"(cgi));
    const int j0  = (int)cgi * 32;
    const int tid = threadIdx.x;
    const int w   = tid >> 5;
    const int l   = tid & 31;
    const int kb  = w * 32;
    const int vc0 = 2 * l;

    // Register-resident duplicated U: 64 x u64 per thread.
    const float* __restrict__ Usrc = (vc0 < 32) ? Uf : Uh;
    const int c0 = j0 + (vc0 & 31);
    u64 uu0[32], uu1[32];
#pragma unroll
    for (int i = 0; i < 32; i++) {
        const float* r = &Usrc[(size_t)(kb + i) * H_SZ + c0];
        float2 uv = *(const float2*)r;
        uu0[i] = dup2(uv.x);
        uu1[i] = dup2(uv.y);
    }
    const float aP = pa[0];

    const unsigned sH_a = smem_u32(&sHp[0][0][0]);
    const unsigned sO_a = smem_u32(&sOut[0][0][0]);
    const unsigned mb_a = smem_u32(&mbar[0]);

    // Zero buffer 0 (both phases; step-0 h = 0); init barriers; pre-post buf 1.
    ((float4*)&sHp[0][0][0])[tid] = make_float4(0.f, 0.f, 0.f, 0.f);
    if (tid == 0) {
#pragma unroll
        for (int s = 0; s < 4; s++)
            asm volatile("mbarrier.init.shared.b64 [%0], 1;"
                         :: "r"(mb_a + 8u * s) : "memory");
        asm volatile("mbarrier.arrive.expect_tx.shared.b64 _, [%0], %1;"
                     :: "r"(mb_a + 8u * 2), "r"(2048u) : "memory");
        asm volatile("mbarrier.arrive.expect_tx.shared.b64 _, [%0], %1;"
                     :: "r"(mb_a + 8u * 3), "r"(2048u) : "memory");
    }
    __syncthreads();
    asm volatile("barrier.cluster.arrive.aligned;" ::: "memory");
    asm volatile("barrier.cluster.wait.aligned;" ::: "memory");

    // Send target for lane r (<8): staggered rank dr = (cgi + r) & 7.
    const unsigned dr = (cgi + (unsigned)(tid & 7)) & 7u;
    unsigned rdst0, rmb0;
    asm("mapa.shared::cluster.u32 %0, %1, %2;" : "=r"(rdst0) : "r"(sH_a), "r"(dr));
    asm("mapa.shared::cluster.u32 %0, %1, %2;" : "=r"(rmb0)  : "r"(mb_a), "r"(dr));

    const int ecol = tid & 31;
    const int bb   = (tid >> 5) & 1;          // batch within phase (tid < 64)

    int par[4] = {0, 0, 0, 0};

    for (int t = 0; t < T_LEN; t++) {
        const int b  = t & 1;
        const int sb = b ^ 1;

#pragma unroll
        for (int p = 0; p < 2; p++) {
            const int mi = b * 2 + p;

            // Prefetch xf/xh for this phase (independent of h).
            float xfv = 0.0f, xhv = 0.0f;
            if (tid < 64) {
                size_t base = ((size_t)t * B_SZ + g * NB + 2 * p + bb) * 512 + j0 + ecol;
                xfv = g_xfh[base];
                xhv = g_xfh[base + 256];
            }

            if (t > 0) {
                const unsigned mb = mb_a + 8u * (unsigned)mi;
                asm volatile(
                    "{\n\t .reg .pred q;\n\t"
                    "LW%=:\n\t"
                    "mbarrier.try_wait.parity.acquire.cluster.shared::cta.b64 q, [%0], %1, 0x989680;\n\t"
                    "@!q bra LW%=;\n\t}"
                    :: "r"(mb), "r"((unsigned)par[mi]) : "memory");
                par[mi] ^= 1;
            }

            const float2* __restrict__ hR = &sHp[b][p][0];

            u64 aa0 = 0ull, aa1 = 0ull;
#pragma unroll
            for (int i = 0; i < 32; i++) {
                u64 hx = *(const u64*)&hR[kb + i];   // (h_{2p}, h_{2p+1})
                fma2(aa0, uu0[i], hx);
                fma2(aa1, uu1[i], hx);
            }
            {
                float2 q0 = u2f(aa0), q1 = u2f(aa1);
                sRed[vc0 * 17 + w]            = q0.x;
                sRed[vc0 * 17 + 8 + w]        = q0.y;
                sRed[(vc0 + 1) * 17 + w]      = q1.x;
                sRed[(vc0 + 1) * 17 + 8 + w]  = q1.y;
            }
            __syncthreads();   // partials visible to epilogue

            // Post expect for (b,p)'s NEXT fill before our phase-p sends
            // (ordered by the pre-send sync below). Skip last two steps.
            if (tid == 0 && t < T_LEN - 2)
                asm volatile("mbarrier.arrive.expect_tx.shared.b64 _, [%0], %1;"
                             :: "r"(mb_a + 8u * (unsigned)mi), "r"(2048u) : "memory");

            if (tid < 64) {
                const float* rf = &sRed[ecol * 17 + bb * 8];
                const float* rh = &sRed[(ecol + 32) * 17 + bb * 8];
                float pf = ((rf[0] + rf[1]) + (rf[2] + rf[3]))
                         + ((rf[4] + rf[5]) + (rf[6] + rf[7])) + xfv;
                float ph = ((rh[0] + rh[1]) + (rh[2] + rh[3]))
                         + ((rh[4] + rh[5]) + (rh[6] + rh[7])) + xhv;

                float f  = 1.0f / (1.0f + expf(-pf));
                float hn = tanhf(ph);
                float ho = ((const float*)&hR[j0 + ecol])[bb];
                float hv = f * ho + (1.0f - f) * hn;
                hv = (hv >= 0.0f) ? hv : aP * hv;

                sOut[sb][p][ecol * 2 + bb] = hv;   // receiver-native (h pairs per k)
                out[((size_t)t * B_SZ + g * NB + 2 * p + bb) * H_SZ + j0 + ecol] = hv;
            }
            __syncthreads();   // staging + expect post visible before copies

            if (tid < 8 && t < T_LEN - 1) {
                asm volatile("fence.proxy.async.shared::cta;" ::: "memory");
                const unsigned src  = sO_a + (unsigned)sb * 512u + (unsigned)p * 256u;
                const unsigned doff = (unsigned)sb * 4096u + (unsigned)p * 2048u
                                    + cgi * 256u;
                const unsigned mbb  = rmb0 + 8u * (unsigned)(sb * 2 + p);
                asm volatile(
                    "cp.async.bulk.shared::cluster.shared::cta.mbarrier::complete_tx::bytes "
                    "[%0], [%1], %2, [%3];"
                    :: "r"(rdst0 + doff), "r"(src), "r"(256u), "r"(mbb)
                    : "memory");
            }
        }
    }

    asm volatile("barrier.cluster.arrive.aligned;" ::: "memory");
    asm volatile("barrier.cluster.wait.aligned;" ::: "memory");
    if (tid == 0) {   // leave raw memory for next graph replay's init
#pragma unroll
        for (int s = 0; s < 4; s++)
            asm volatile("mbarrier.inval.shared.b64 [%0];"
                         :: "r"(mb_a + 8u * s) : "memory");
    }
}

// ---------------- launch ------------------------------------------------------
extern "C" void kernel_launch(void* const* d_in, const int* in_sizes, int n_in,
                              void* d_out, int out_size) {
    (void)in_sizes; (void)n_in; (void)out_size;
    const float* seq = (const float*)d_in[0];
    const float* Wf  = (const float*)d_in[1];
    const float* Uf  = (const float*)d_in[2];
    const float* bf  = (const float*)d_in[3];
    const float* Wh  = (const float*)d_in[4];
    const float* Uh  = (const float*)d_in[5];
    const float* bh  = (const float*)d_in[6];
    const float* pa  = (const float*)d_in[7];
    float* out = (float*)d_out;

    dim3 pgrid(T_LEN * B_SZ / 128, 4);
    proj_kernel<<<pgrid, 256>>>(seq, Wf, bf, Wh, bh);

    rec_kernel<<<NGRP * CPG, 256>>>(Uf, Uh, pa, out);
}

// round 10
// speedup vs baseline: 1.1410x; 1.1410x over previous
#include <cuda_runtime.h>
#include <math.h>

#define T_LEN 2048
#define B_SZ  64
#define I_SZ  256
#define H_SZ  256

#define NGRP 16
#define CPG  8     // CTAs per group = cluster size
#define NB   4     // batches per group

typedef unsigned long long u64;

__device__ __forceinline__ void fma2(u64 &d, u64 a, u64 b) {
    asm("fma.rn.f32x2 %0, %1, %2, %0;" : "+l"(d) : "l"(a), "l"(b));
}
__device__ __forceinline__ float2 u2f(u64 v) {
    float2 r; asm("mov.b64 {%0, %1}, %2;" : "=f"(r.x), "=f"(r.y) : "l"(v)); return r;
}
__device__ __forceinline__ u64 dup2(float x) {
    u64 r; asm("mov.b64 %0, {%1, %1};" : "=l"(r) : "f"(x)); return r;
}
__device__ __forceinline__ unsigned smem_u32(const void* p) {
    unsigned a;
    asm("{ .reg .u64 t; cvta.to.shared.u64 t, %1; cvt.u32.u64 %0, t; }" : "=r"(a) : "l"(p));
    return a;
}
// Fast sigmoid / tanh via ex2.approx + rcp.approx (rel err ~2^-22).
__device__ __forceinline__ float fast_sigmoid(float x) {
    x = fminf(fmaxf(x, -20.f), 20.f);
    float e, r;
    asm("ex2.approx.f32 %0, %1;" : "=f"(e) : "f"(-x * 1.4426950408889634f));
    asm("rcp.approx.f32 %0, %1;" : "=f"(r) : "f"(e + 1.0f));
    return r;
}
__device__ __forceinline__ float fast_tanh(float x) {
    x = fminf(fmaxf(x, -15.f), 15.f);
    float e, r;
    asm("ex2.approx.f32 %0, %1;" : "=f"(e) : "f"(x * 2.8853900817779268f));  // e^{2x}
    asm("rcp.approx.f32 %0, %1;" : "=f"(r) : "f"(e + 1.0f));
    return (e - 1.0f) * r;
}

// ---------------- scratch ----------------------------------------------------
__device__ float g_xfh[(size_t)T_LEN * B_SZ * 512];   // [t][b][0:256]=xf, [256:512]=xh

// ---------------- projection GEMM (double-buffered, f32x2) -------------------
__global__ __launch_bounds__(256) void proj_kernel(
    const float* __restrict__ seq,
    const float* __restrict__ Wf, const float* __restrict__ bf,
    const float* __restrict__ Wh, const float* __restrict__ bh)
{
    __shared__ float2 As2[2][8][130];
    __shared__ float  Bs[2][8][132];

    const int bm = blockIdx.x;
    const int bn = blockIdx.y;
    const float* __restrict__ W    = (bn < 2) ? Wf : Wh;
    const float* __restrict__ bias = (bn < 2) ? bf : bh;
    const int nb = (bn & 1) * 128;

    const int tid  = threadIdx.x;
    const int tx   = tid & 15;
    const int ty   = tid >> 4;
    const int arow = tid >> 1, acol = (tid & 1) * 4;
    const int brow = tid >> 5, bcol = (tid & 31) * 4;
    const size_t abase = (size_t)(bm * 128 + arow) * 256 + acol;

    u64 acc[8][4];
#pragma unroll
    for (int i = 0; i < 8; i++)
#pragma unroll
        for (int j = 0; j < 4; j++) acc[i][j] = 0ull;

    {
        float4 av = *(const float4*)&seq[abase];
        float4 bv = *(const float4*)&W[(size_t)brow * 256 + nb + bcol];
        As2[0][acol + 0][arow] = make_float2(av.x, av.x);
        As2[0][acol + 1][arow] = make_float2(av.y, av.y);
        As2[0][acol + 2][arow] = make_float2(av.z, av.z);
        As2[0][acol + 3][arow] = make_float2(av.w, av.w);
        *(float4*)&Bs[0][brow][bcol] = bv;
    }
    __syncthreads();

    for (int it = 0; it < 32; it++) {
        const int p = it & 1;
        float4 av, bv;
        if (it < 31) {
            const int k0 = (it + 1) * 8;
            av = *(const float4*)&seq[abase + k0];
            bv = *(const float4*)&W[(size_t)(k0 + brow) * 256 + nb + bcol];
        }
#pragma unroll
        for (int k = 0; k < 8; k++) {
            ulonglong2 a01 = *(const ulonglong2*)&As2[p][k][ty * 8 + 0];
            ulonglong2 a23 = *(const ulonglong2*)&As2[p][k][ty * 8 + 2];
            ulonglong2 a45 = *(const ulonglong2*)&As2[p][k][ty * 8 + 4];
            ulonglong2 a67 = *(const ulonglong2*)&As2[p][k][ty * 8 + 6];
            ulonglong2 b01 = *(const ulonglong2*)&Bs[p][k][tx * 8];
            ulonglong2 b23 = *(const ulonglong2*)&Bs[p][k][tx * 8 + 4];
            u64 ad[8] = {a01.x, a01.y, a23.x, a23.y, a45.x, a45.y, a67.x, a67.y};
#pragma unroll
            for (int i = 0; i < 8; i++) {
                fma2(acc[i][0], ad[i], b01.x);
                fma2(acc[i][1], ad[i], b01.y);
                fma2(acc[i][2], ad[i], b23.x);
                fma2(acc[i][3], ad[i], b23.y);
            }
        }
        if (it < 31) {
            const int np = p ^ 1;
            As2[np][acol + 0][arow] = make_float2(av.x, av.x);
            As2[np][acol + 1][arow] = make_float2(av.y, av.y);
            As2[np][acol + 2][arow] = make_float2(av.z, av.z);
            As2[np][acol + 3][arow] = make_float2(av.w, av.w);
            *(float4*)&Bs[np][brow][bcol] = bv;
        }
        __syncthreads();
    }

    float bb[8];
#pragma unroll
    for (int j = 0; j < 8; j++) bb[j] = bias[nb + tx * 8 + j];

#pragma unroll
    for (int i = 0; i < 8; i++) {
        size_t m = (size_t)bm * 128 + ty * 8 + i;
        float* op = &g_xfh[m * 512 + (size_t)bn * 128 + tx * 8];
        float2 c0 = u2f(acc[i][0]), c1 = u2f(acc[i][1]);
        float2 c2 = u2f(acc[i][2]), c3 = u2f(acc[i][3]);
        float4 v0, v1;
        v0.x = c0.x + bb[0]; v0.y = c0.y + bb[1];
        v0.z = c1.x + bb[2]; v0.w = c1.y + bb[3];
        v1.x = c2.x + bb[4]; v1.y = c2.y + bb[5];
        v1.z = c3.x + bb[6]; v1.w = c3.y + bb[7];
        *(float4*)&op[0] = v0;
        *(float4*)&op[4] = v1;
    }
}

// ---------------- persistent recurrence (R8 base + deep prefetch + fast act) -
__global__ __launch_bounds__(256, 1) __cluster_dims__(CPG, 1, 1)
void rec_kernel(const float* __restrict__ Uf, const float* __restrict__ Uh,
                const float* __restrict__ pa, float* __restrict__ out)
{
    __shared__ float4 sHp[2][256];                     // 8 KB recv: [buf][k]=(h0..h3)
    __shared__ float  sRed[64 * 33];                   // 8.4 KB
    __shared__ __align__(16) float sOut[2][128];       // 1 KB staging
    __shared__ __align__(16) u64 mbar[2][CPG];         // per-buffer, per-source

    const int g   = blockIdx.x >> 3;
    unsigned cgi;
    asm("mov.u32 %0, %%cluster_ctarank;" : "=r"(cgi));
    const int j0  = (int)cgi * 32;
    const int tid = threadIdx.x;
    const int w   = tid >> 5;
    const int l   = tid & 31;
    const int kb  = w * 32;
    const int vc0 = 2 * l;

    // Register-resident duplicated U: 64 x u64 per thread.
    const float* __restrict__ Usrc = (vc0 < 32) ? Uf : Uh;
    const int c0 = j0 + (vc0 & 31);
    u64 uu0[32], uu1[32];
#pragma unroll
    for (int i = 0; i < 32; i++) {
        const float* r = &Usrc[(size_t)(kb + i) * H_SZ + c0];
        float2 uv = *(const float2*)r;
        uu0[i] = dup2(uv.x);
        uu1[i] = dup2(uv.y);
    }
    const float aP = pa[0];

    const unsigned sH_a = smem_u32(&sHp[0][0]);
    const unsigned sO_a = smem_u32(&sOut[0][0]);
    const unsigned mb_a = smem_u32(&mbar[0][0]);

    // Zero buffer 0 (step-0 h = 0); init barriers; pre-post expects for buf 1.
    sHp[0][tid] = make_float4(0.f, 0.f, 0.f, 0.f);
    if (tid == 0) {
#pragma unroll
        for (int s = 0; s < 2 * CPG; s++)
            asm volatile("mbarrier.init.shared.b64 [%0], 1;"
                         :: "r"(mb_a + 8u * s) : "memory");
#pragma unroll
        for (int s = 0; s < CPG; s++)   // buffer 1 first fill (sent at end of t=0)
            asm volatile("mbarrier.arrive.expect_tx.shared.b64 _, [%0], %1;"
                         :: "r"(mb_a + 8u * (CPG + s)), "r"(512u) : "memory");
    }
    __syncthreads();
    asm volatile("barrier.cluster.arrive.aligned;" ::: "memory");
    asm volatile("barrier.cluster.wait.aligned;" ::: "memory");

    // Send target for lane r (<8): staggered rank dr = (cgi + r) & 7.
    const unsigned dr = (cgi + (unsigned)(tid & 7)) & 7u;
    unsigned rdst0, rmb0;
    asm("mapa.shared::cluster.u32 %0, %1, %2;" : "=r"(rdst0) : "r"(sH_a), "r"(dr));
    asm("mapa.shared::cluster.u32 %0, %1, %2;" : "=r"(rmb0)  : "r"(mb_a), "r"(dr));

    const int ecol = tid & 31;
    const int eb   = tid >> 5;                // valid for tid < 128

    // Deep prefetch: xf/xh for step t are loaded at the top of step t-1.
    const size_t xstride = (size_t)B_SZ * 512;
    const size_t xbase0  = ((size_t)(g * NB + eb)) * 512 + j0 + ecol;
    float xfv = 0.f, xhv = 0.f;
    if (tid < 128) {
        xfv = g_xfh[xbase0];          // t = 0
        xhv = g_xfh[xbase0 + 256];
    }

    int par[2] = {0, 0};

    for (int t = 0; t < T_LEN; t++) {
        const int b = t & 1;

        // Issue NEXT step's xf/xh loads now (~full step of latency cover).
        float xfn = 0.f, xhn = 0.f;
        if (tid < 128) {
            const size_t tt = (t + 1 < T_LEN) ? (size_t)(t + 1) : (size_t)t;
            xfn = g_xfh[tt * xstride + xbase0];
            xhn = g_xfh[tt * xstride + xbase0 + 256];
        }

        if (t > 0) {   // warp w waits ONLY for its own source chunk
            const unsigned mb = mb_a + 8u * (unsigned)(b * CPG + w);
            asm volatile(
                "{\n\t .reg .pred p;\n\t"
                "LW%=:\n\t"
                "mbarrier.try_wait.parity.acquire.cluster.shared::cta.b64 p, [%0], %1, 0x989680;\n\t"
                "@!p bra LW%=;\n\t}"
                :: "r"(mb), "r"((unsigned)par[b]) : "memory");
            par[b] ^= 1;
        }

        const float4* __restrict__ hR = &sHp[b][0];

        u64 a00 = 0ull, a01v = 0ull, a10 = 0ull, a11 = 0ull;
#pragma unroll
        for (int i = 0; i < 32; i++) {
            ulonglong2 hp = *(const ulonglong2*)&hR[kb + i];  // (h0,h1),(h2,h3)
            fma2(a00,  uu0[i], hp.x);
            fma2(a01v, uu0[i], hp.y);
            fma2(a10,  uu1[i], hp.x);
            fma2(a11,  uu1[i], hp.y);
        }
        {
            float2 p00 = u2f(a00), p01 = u2f(a01v), p10 = u2f(a10), p11 = u2f(a11);
            float* r0 = &sRed[vc0 * 33 + w];
            float* r1 = &sRed[(vc0 + 1) * 33 + w];
            r0[0]  = p00.x; r0[8]  = p00.y; r0[16] = p01.x; r0[24] = p01.y;
            r1[0]  = p10.x; r1[8]  = p10.y; r1[16] = p11.x; r1[24] = p11.y;
        }
        __syncthreads();   // partials visible; all source chunks now arrived

        // Post expects for buffer b's NEXT fill before our sends (ordered by
        // the pre-send sync below). Skip last two steps -> barriers end clean.
        if (tid < 8 && t < T_LEN - 2)
            asm volatile("mbarrier.arrive.expect_tx.shared.b64 _, [%0], %1;"
                         :: "r"(mb_a + 8u * (unsigned)(b * CPG + tid)), "r"(512u)
                         : "memory");

        const int sb = (t + 1) & 1;   // staging/send buffer
        float hv = 0.0f;
        if (tid < 128) {
            const float* rf = &sRed[ecol * 33 + eb * 8];
            const float* rh = &sRed[(ecol + 32) * 33 + eb * 8];
            float pf = ((rf[0] + rf[1]) + (rf[2] + rf[3]))
                     + ((rf[4] + rf[5]) + (rf[6] + rf[7])) + xfv;
            float ph = ((rh[0] + rh[1]) + (rh[2] + rh[3]))
                     + ((rh[4] + rh[5]) + (rh[6] + rh[7])) + xhv;

            float f  = fast_sigmoid(pf);
            float hn = fast_tanh(ph);
            float ho = ((const float*)hR)[(j0 + ecol) * 4 + eb];
            hv = f * ho + (1.0f - f) * hn;
            hv = (hv >= 0.0f) ? hv : aP * hv;

            sOut[sb][ecol * 4 + eb] = hv;   // receiver-native layout
        }
        __syncthreads();   // staging + expect posts visible before copies

        if (t < T_LEN - 1) {
            if (tid < 32)
                asm volatile("fence.proxy.async.shared::cta;" ::: "memory");
            if (tid < 8) {   // lane r -> rank (cgi+r)&7; signals their mbar[sb][cgi]
                const unsigned src  = sO_a + (unsigned)sb * 512u;
                const unsigned doff = (unsigned)sb * 4096u + cgi * 512u;
                const unsigned mbb  = rmb0 + 8u * ((unsigned)sb * CPG + cgi);
                asm volatile(
                    "cp.async.bulk.shared::cluster.shared::cta.mbarrier::complete_tx::bytes "
                    "[%0], [%1], %2, [%3];"
                    :: "r"(rdst0 + doff), "r"(src), "r"(512u), "r"(mbb)
                    : "memory");
            }
        }
        // Global store off the critical path (after send issue).
        if (tid < 128)
            out[((size_t)t * B_SZ + g * NB + eb) * H_SZ + j0 + ecol] = hv;

        xfv = xfn;
        xhv = xhn;
    }

    asm volatile("barrier.cluster.arrive.aligned;" ::: "memory");
    asm volatile("barrier.cluster.wait.aligned;" ::: "memory");
    if (tid == 0) {   // leave raw memory for next graph replay's init
#pragma unroll
        for (int s = 0; s < 2 * CPG; s++)
            asm volatile("mbarrier.inval.shared.b64 [%0];"
                         :: "r"(mb_a + 8u * s) : "memory");
    }
}

// ---------------- launch ------------------------------------------------------
extern "C" void kernel_launch(void* const* d_in, const int* in_sizes, int n_in,
                              void* d_out, int out_size) {
    (void)in_sizes; (void)n_in; (void)out_size;
    const float* seq = (const float*)d_in[0];
    const float* Wf  = (const float*)d_in[1];
    const float* Uf  = (const float*)d_in[2];
    const float* bf  = (const float*)d_in[3];
    const float* Wh  = (const float*)d_in[4];
    const float* Uh  = (const float*)d_in[5];
    const float* bh  = (const float*)d_in[6];
    const float* pa  = (const float*)d_in[7];
    float* out = (float*)d_out;

    dim3 pgrid(T_LEN * B_SZ / 128, 4);
    proj_kernel<<<pgrid, 256>>>(seq, Wf, bf, Wh, bh);

    rec_kernel<<<NGRP * CPG, 256>>>(Uf, Uh, pa, out);
}

// round 11
// speedup vs baseline: 1.2348x; 1.0822x over previous
#include <cuda_runtime.h>
#include <math.h>

#define T_LEN 2048
#define B_SZ  64
#define I_SZ  256
#define H_SZ  256

#define NGRP 16
#define CPG  8     // CTAs per group = cluster size
#define NB   4     // batches per group

typedef unsigned long long u64;

__device__ __forceinline__ void fma2(u64 &d, u64 a, u64 b) {
    asm("fma.rn.f32x2 %0, %1, %2, %0;" : "+l"(d) : "l"(a), "l"(b));
}
__device__ __forceinline__ float2 u2f(u64 v) {
    float2 r; asm("mov.b64 {%0, %1}, %2;" : "=f"(r.x), "=f"(r.y) : "l"(v)); return r;
}
__device__ __forceinline__ u64 dup2(float x) {
    u64 r; asm("mov.b64 %0, {%1, %1};" : "=l"(r) : "f"(x)); return r;
}
__device__ __forceinline__ unsigned smem_u32(const void* p) {
    unsigned a;
    asm("{ .reg .u64 t; cvta.to.shared.u64 t, %1; cvt.u32.u64 %0, t; }" : "=r"(a) : "l"(p));
    return a;
}
// Fast sigmoid / tanh via ex2.approx + rcp.approx (rel err ~2^-22).
__device__ __forceinline__ float fast_sigmoid(float x) {
    x = fminf(fmaxf(x, -20.f), 20.f);
    float e, r;
    asm("ex2.approx.f32 %0, %1;" : "=f"(e) : "f"(-x * 1.4426950408889634f));
    asm("rcp.approx.f32 %0, %1;" : "=f"(r) : "f"(e + 1.0f));
    return r;
}
__device__ __forceinline__ float fast_tanh(float x) {
    x = fminf(fmaxf(x, -15.f), 15.f);
    float e, r;
    asm("ex2.approx.f32 %0, %1;" : "=f"(e) : "f"(x * 2.8853900817779268f));  // e^{2x}
    asm("rcp.approx.f32 %0, %1;" : "=f"(r) : "f"(e + 1.0f));
    return (e - 1.0f) * r;
}

// ---------------- scratch ----------------------------------------------------
__device__ float g_xfh[(size_t)T_LEN * B_SZ * 512];   // [t][b][0:256]=xf, [256:512]=xh

// ---------------- projection GEMM (double-buffered, f32x2) -------------------
__global__ __launch_bounds__(256) void proj_kernel(
    const float* __restrict__ seq,
    const float* __restrict__ Wf, const float* __restrict__ bf,
    const float* __restrict__ Wh, const float* __restrict__ bh)
{
    __shared__ float2 As2[2][8][130];
    __shared__ float  Bs[2][8][132];

    const int bm = blockIdx.x;
    const int bn = blockIdx.y;
    const float* __restrict__ W    = (bn < 2) ? Wf : Wh;
    const float* __restrict__ bias = (bn < 2) ? bf : bh;
    const int nb = (bn & 1) * 128;

    const int tid  = threadIdx.x;
    const int tx   = tid & 15;
    const int ty   = tid >> 4;
    const int arow = tid >> 1, acol = (tid & 1) * 4;
    const int brow = tid >> 5, bcol = (tid & 31) * 4;
    const size_t abase = (size_t)(bm * 128 + arow) * 256 + acol;

    u64 acc[8][4];
#pragma unroll
    for (int i = 0; i < 8; i++)
#pragma unroll
        for (int j = 0; j < 4; j++) acc[i][j] = 0ull;

    {
        float4 av = *(const float4*)&seq[abase];
        float4 bv = *(const float4*)&W[(size_t)brow * 256 + nb + bcol];
        As2[0][acol + 0][arow] = make_float2(av.x, av.x);
        As2[0][acol + 1][arow] = make_float2(av.y, av.y);
        As2[0][acol + 2][arow] = make_float2(av.z, av.z);
        As2[0][acol + 3][arow] = make_float2(av.w, av.w);
        *(float4*)&Bs[0][brow][bcol] = bv;
    }
    __syncthreads();

    for (int it = 0; it < 32; it++) {
        const int p = it & 1;
        float4 av, bv;
        if (it < 31) {
            const int k0 = (it + 1) * 8;
            av = *(const float4*)&seq[abase + k0];
            bv = *(const float4*)&W[(size_t)(k0 + brow) * 256 + nb + bcol];
        }
#pragma unroll
        for (int k = 0; k < 8; k++) {
            ulonglong2 a01 = *(const ulonglong2*)&As2[p][k][ty * 8 + 0];
            ulonglong2 a23 = *(const ulonglong2*)&As2[p][k][ty * 8 + 2];
            ulonglong2 a45 = *(const ulonglong2*)&As2[p][k][ty * 8 + 4];
            ulonglong2 a67 = *(const ulonglong2*)&As2[p][k][ty * 8 + 6];
            ulonglong2 b01 = *(const ulonglong2*)&Bs[p][k][tx * 8];
            ulonglong2 b23 = *(const ulonglong2*)&Bs[p][k][tx * 8 + 4];
            u64 ad[8] = {a01.x, a01.y, a23.x, a23.y, a45.x, a45.y, a67.x, a67.y};
#pragma unroll
            for (int i = 0; i < 8; i++) {
                fma2(acc[i][0], ad[i], b01.x);
                fma2(acc[i][1], ad[i], b01.y);
                fma2(acc[i][2], ad[i], b23.x);
                fma2(acc[i][3], ad[i], b23.y);
            }
        }
        if (it < 31) {
            const int np = p ^ 1;
            As2[np][acol + 0][arow] = make_float2(av.x, av.x);
            As2[np][acol + 1][arow] = make_float2(av.y, av.y);
            As2[np][acol + 2][arow] = make_float2(av.z, av.z);
            As2[np][acol + 3][arow] = make_float2(av.w, av.w);
            *(float4*)&Bs[np][brow][bcol] = bv;
        }
        __syncthreads();
    }

    float bb[8];
#pragma unroll
    for (int j = 0; j < 8; j++) bb[j] = bias[nb + tx * 8 + j];

#pragma unroll
    for (int i = 0; i < 8; i++) {
        size_t m = (size_t)bm * 128 + ty * 8 + i;
        float* op = &g_xfh[m * 512 + (size_t)bn * 128 + tx * 8];
        float2 c0 = u2f(acc[i][0]), c1 = u2f(acc[i][1]);
        float2 c2 = u2f(acc[i][2]), c3 = u2f(acc[i][3]);
        float4 v0, v1;
        v0.x = c0.x + bb[0]; v0.y = c0.y + bb[1];
        v0.z = c1.x + bb[2]; v0.w = c1.y + bb[3];
        v1.x = c2.x + bb[4]; v1.y = c2.y + bb[5];
        v1.z = c3.x + bb[6]; v1.w = c3.y + bb[7];
        *(float4*)&op[0] = v0;
        *(float4*)&op[4] = v1;
    }
}

// ---------------- persistent recurrence (R10 base, st.async.v2.b64 exchange) -
// Same per-source mbarrier protocol; transport = direct DSMEM st.async
// (warp 0: lane l owns float4 #l; one 512B warp-instruction per dest rank).
__global__ __launch_bounds__(256, 1) __cluster_dims__(CPG, 1, 1)
void rec_kernel(const float* __restrict__ Uf, const float* __restrict__ Uh,
                const float* __restrict__ pa, float* __restrict__ out)
{
    __shared__ float4 sHp[2][256];                     // 8 KB recv: [buf][k]=(h0..h3)
    __shared__ float  sRed[64 * 33];                   // 8.4 KB
    __shared__ __align__(16) float sOut[2][128];       // 1 KB staging
    __shared__ __align__(16) u64 mbar[2][CPG];         // per-buffer, per-source

    const int g   = blockIdx.x >> 3;
    unsigned cgi;
    asm("mov.u32 %0, %%cluster_ctarank;" : "=r"(cgi));
    const int j0  = (int)cgi * 32;
    const int tid = threadIdx.x;
    const int w   = tid >> 5;
    const int l   = tid & 31;
    const int kb  = w * 32;
    const int vc0 = 2 * l;

    // Register-resident duplicated U: 64 x u64 per thread.
    const float* __restrict__ Usrc = (vc0 < 32) ? Uf : Uh;
    const int c0 = j0 + (vc0 & 31);
    u64 uu0[32], uu1[32];
#pragma unroll
    for (int i = 0; i < 32; i++) {
        const float* r = &Usrc[(size_t)(kb + i) * H_SZ + c0];
        float2 uv = *(const float2*)r;
        uu0[i] = dup2(uv.x);
        uu1[i] = dup2(uv.y);
    }
    const float aP = pa[0];

    const unsigned sH_a = smem_u32(&sHp[0][0]);
    const unsigned mb_a = smem_u32(&mbar[0][0]);

    // Zero buffer 0 (step-0 h = 0); init barriers; pre-post expects for buf 1.
    sHp[0][tid] = make_float4(0.f, 0.f, 0.f, 0.f);
    if (tid == 0) {
#pragma unroll
        for (int s = 0; s < 2 * CPG; s++)
            asm volatile("mbarrier.init.shared.b64 [%0], 1;"
                         :: "r"(mb_a + 8u * s) : "memory");
#pragma unroll
        for (int s = 0; s < CPG; s++)   // buffer 1 first fill (sent at end of t=0)
            asm volatile("mbarrier.arrive.expect_tx.shared.b64 _, [%0], %1;"
                         :: "r"(mb_a + 8u * (CPG + s)), "r"(512u) : "memory");
    }
    __syncthreads();
    asm volatile("barrier.cluster.arrive.aligned;" ::: "memory");
    asm volatile("barrier.cluster.wait.aligned;" ::: "memory");

    // All-rank remote addresses, staggered start (r -> rank (cgi+r)&7).
    unsigned rbase[CPG], rmb[CPG];
#pragma unroll
    for (int r = 0; r < CPG; r++) {
        const unsigned rr = (cgi + (unsigned)r) & 7u;
        asm("mapa.shared::cluster.u32 %0, %1, %2;" : "=r"(rbase[r]) : "r"(sH_a), "r"(rr));
        asm("mapa.shared::cluster.u32 %0, %1, %2;" : "=r"(rmb[r])  : "r"(mb_a), "r"(rr));
    }

    const int ecol = tid & 31;
    const int eb   = tid >> 5;                // valid for tid < 128

    // Deep prefetch: xf/xh for step t are loaded at the top of step t-1.
    const size_t xstride = (size_t)B_SZ * 512;
    const size_t xbase0  = ((size_t)(g * NB + eb)) * 512 + j0 + ecol;
    float xfv = 0.f, xhv = 0.f;
    if (tid < 128) {
        xfv = g_xfh[xbase0];          // t = 0
        xhv = g_xfh[xbase0 + 256];
    }

    int par[2] = {0, 0};

    for (int t = 0; t < T_LEN; t++) {
        const int b = t & 1;

        // Issue NEXT step's xf/xh loads now (~full step of latency cover).
        float xfn = 0.f, xhn = 0.f;
        if (tid < 128) {
            const size_t tt = (t + 1 < T_LEN) ? (size_t)(t + 1) : (size_t)t;
            xfn = g_xfh[tt * xstride + xbase0];
            xhn = g_xfh[tt * xstride + xbase0 + 256];
        }

        if (t > 0) {   // warp w waits ONLY for its own source chunk
            const unsigned mb = mb_a + 8u * (unsigned)(b * CPG + w);
            asm volatile(
                "{\n\t .reg .pred p;\n\t"
                "LW%=:\n\t"
                "mbarrier.try_wait.parity.acquire.cluster.shared::cta.b64 p, [%0], %1, 0x989680;\n\t"
                "@!p bra LW%=;\n\t}"
                :: "r"(mb), "r"((unsigned)par[b]) : "memory");
            par[b] ^= 1;
        }

        const float4* __restrict__ hR = &sHp[b][0];

        u64 a00 = 0ull, a01v = 0ull, a10 = 0ull, a11 = 0ull;
#pragma unroll
        for (int i = 0; i < 32; i++) {
            ulonglong2 hp = *(const ulonglong2*)&hR[kb + i];  // (h0,h1),(h2,h3)
            fma2(a00,  uu0[i], hp.x);
            fma2(a01v, uu0[i], hp.y);
            fma2(a10,  uu1[i], hp.x);
            fma2(a11,  uu1[i], hp.y);
        }
        {
            float2 p00 = u2f(a00), p01 = u2f(a01v), p10 = u2f(a10), p11 = u2f(a11);
            float* r0 = &sRed[vc0 * 33 + w];
            float* r1 = &sRed[(vc0 + 1) * 33 + w];
            r0[0]  = p00.x; r0[8]  = p00.y; r0[16] = p01.x; r0[24] = p01.y;
            r1[0]  = p10.x; r1[8]  = p10.y; r1[16] = p11.x; r1[24] = p11.y;
        }
        __syncthreads();   // partials visible; all source chunks now arrived

        // Post expects for buffer b's NEXT fill before our sends (ordered by
        // the pre-send sync below). Skip last two steps -> barriers end clean.
        if (tid < 8 && t < T_LEN - 2)
            asm volatile("mbarrier.arrive.expect_tx.shared.b64 _, [%0], %1;"
                         :: "r"(mb_a + 8u * (unsigned)(b * CPG + tid)), "r"(512u)
                         : "memory");

        const int sb = (t + 1) & 1;   // staging/send buffer
        float hv = 0.0f;
        if (tid < 128) {
            const float* rf = &sRed[ecol * 33 + eb * 8];
            const float* rh = &sRed[(ecol + 32) * 33 + eb * 8];
            float pf = ((rf[0] + rf[1]) + (rf[2] + rf[3]))
                     + ((rf[4] + rf[5]) + (rf[6] + rf[7])) + xfv;
            float ph = ((rh[0] + rh[1]) + (rh[2] + rh[3]))
                     + ((rh[4] + rh[5]) + (rh[6] + rh[7])) + xhv;

            float f  = fast_sigmoid(pf);
            float hn = fast_tanh(ph);
            float ho = ((const float*)hR)[(j0 + ecol) * 4 + eb];
            hv = f * ho + (1.0f - f) * hn;
            hv = (hv >= 0.0f) ? hv : aP * hv;

            sOut[sb][ecol * 4 + eb] = hv;   // receiver-native layout
        }
        __syncthreads();   // staging + expect posts visible before sends

        if (t < T_LEN - 1 && tid < 32) {
            // Lane l owns float4 #l (16 B) of the 512 B payload; one
            // st.async.v2.b64 warp-instruction per destination rank.
            ulonglong2 pay = *(const ulonglong2*)&sOut[sb][tid * 4];
            const unsigned doff = (unsigned)sb * 4096u + cgi * 512u
                                + (unsigned)tid * 16u;
            const unsigned mbo  = 8u * ((unsigned)sb * CPG + cgi);
#pragma unroll
            for (int r = 0; r < CPG; r++) {
                asm volatile(
                    "st.async.shared::cluster.mbarrier::complete_tx::bytes.v2.b64 "
                    "[%0], {%1, %2}, [%3];"
                    :: "r"(rbase[r] + doff), "l"(pay.x), "l"(pay.y),
                       "r"(rmb[r] + mbo)
                    : "memory");
            }
        }
        // Global store off the critical path (after send issue).
        if (tid < 128)
            out[((size_t)t * B_SZ + g * NB + eb) * H_SZ + j0 + ecol] = hv;

        xfv = xfn;
        xhv = xhn;
    }

    asm volatile("barrier.cluster.arrive.aligned;" ::: "memory");
    asm volatile("barrier.cluster.wait.aligned;" ::: "memory");
    if (tid == 0) {   // leave raw memory for next graph replay's init
#pragma unroll
        for (int s = 0; s < 2 * CPG; s++)
            asm volatile("mbarrier.inval.shared.b64 [%0];"
                         :: "r"(mb_a + 8u * s) : "memory");
    }
}

// ---------------- launch ------------------------------------------------------
extern "C" void kernel_launch(void* const* d_in, const int* in_sizes, int n_in,
                              void* d_out, int out_size) {
    (void)in_sizes; (void)n_in; (void)out_size;
    const float* seq = (const float*)d_in[0];
    const float* Wf  = (const float*)d_in[1];
    const float* Uf  = (const float*)d_in[2];
    const float* bf  = (const float*)d_in[3];
    const float* Wh  = (const float*)d_in[4];
    const float* Uh  = (const float*)d_in[5];
    const float* bh  = (const float*)d_in[6];
    const float* pa  = (const float*)d_in[7];
    float* out = (float*)d_out;

    dim3 pgrid(T_LEN * B_SZ / 128, 4);
    proj_kernel<<<pgrid, 256>>>(seq, Wf, bf, Wh, bh);

    rec_kernel<<<NGRP * CPG, 256>>>(Uf, Uh, pa, out);
}

// round 12
// speedup vs baseline: 1.6749x; 1.3564x over previous
#include <cuda_runtime.h>
#include <math.h>

#define T_LEN 2048
#define B_SZ  64
#define I_SZ  256
#define H_SZ  256

#define NGRP 32
#define CPG  8     // CTAs per group = cluster size
#define NB   2     // batches per group

typedef unsigned long long u64;

__device__ __forceinline__ void fma2(u64 &d, u64 a, u64 b) {
    asm("fma.rn.f32x2 %0, %1, %2, %0;" : "+l"(d) : "l"(a), "l"(b));
}
__device__ __forceinline__ float2 u2f(u64 v) {
    float2 r; asm("mov.b64 {%0, %1}, %2;" : "=f"(r.x), "=f"(r.y) : "l"(v)); return r;
}
__device__ __forceinline__ unsigned smem_u32(const void* p) {
    unsigned a;
    asm("{ .reg .u64 t; cvta.to.shared.u64 t, %1; cvt.u32.u64 %0, t; }" : "=r"(a) : "l"(p));
    return a;
}
// Fast sigmoid / tanh via ex2.approx + rcp.approx (rel err ~2^-22).
__device__ __forceinline__ float fast_sigmoid(float x) {
    x = fminf(fmaxf(x, -20.f), 20.f);
    float e, r;
    asm("ex2.approx.f32 %0, %1;" : "=f"(e) : "f"(-x * 1.4426950408889634f));
    asm("rcp.approx.f32 %0, %1;" : "=f"(r) : "f"(e + 1.0f));
    return r;
}
__device__ __forceinline__ float fast_tanh(float x) {
    x = fminf(fmaxf(x, -15.f), 15.f);
    float e, r;
    asm("ex2.approx.f32 %0, %1;" : "=f"(e) : "f"(x * 2.8853900817779268f));  // e^{2x}
    asm("rcp.approx.f32 %0, %1;" : "=f"(r) : "f"(e + 1.0f));
    return (e - 1.0f) * r;
}

// ---------------- scratch ----------------------------------------------------
__device__ float g_xfh[(size_t)T_LEN * B_SZ * 512];   // [t][b][0:256]=xf, [256:512]=xh

// ---------------- projection GEMM (double-buffered, f32x2) -------------------
__global__ __launch_bounds__(256) void proj_kernel(
    const float* __restrict__ seq,
    const float* __restrict__ Wf, const float* __restrict__ bf,
    const float* __restrict__ Wh, const float* __restrict__ bh)
{
    __shared__ float2 As2[2][8][130];
    __shared__ float  Bs[2][8][132];

    const int bm = blockIdx.x;
    const int bn = blockIdx.y;
    const float* __restrict__ W    = (bn < 2) ? Wf : Wh;
    const float* __restrict__ bias = (bn < 2) ? bf : bh;
    const int nb = (bn & 1) * 128;

    const int tid  = threadIdx.x;
    const int tx   = tid & 15;
    const int ty   = tid >> 4;
    const int arow = tid >> 1, acol = (tid & 1) * 4;
    const int brow = tid >> 5, bcol = (tid & 31) * 4;
    const size_t abase = (size_t)(bm * 128 + arow) * 256 + acol;

    u64 acc[8][4];
#pragma unroll
    for (int i = 0; i < 8; i++)
#pragma unroll
        for (int j = 0; j < 4; j++) acc[i][j] = 0ull;

    {
        float4 av = *(const float4*)&seq[abase];
        float4 bv = *(const float4*)&W[(size_t)brow * 256 + nb + bcol];
        As2[0][acol + 0][arow] = make_float2(av.x, av.x);
        As2[0][acol + 1][arow] = make_float2(av.y, av.y);
        As2[0][acol + 2][arow] = make_float2(av.z, av.z);
        As2[0][acol + 3][arow] = make_float2(av.w, av.w);
        *(float4*)&Bs[0][brow][bcol] = bv;
    }
    __syncthreads();

    for (int it = 0; it < 32; it++) {
        const int p = it & 1;
        float4 av, bv;
        if (it < 31) {
            const int k0 = (it + 1) * 8;
            av = *(const float4*)&seq[abase + k0];
            bv = *(const float4*)&W[(size_t)(k0 + brow) * 256 + nb + bcol];
        }
#pragma unroll
        for (int k = 0; k < 8; k++) {
            ulonglong2 a01 = *(const ulonglong2*)&As2[p][k][ty * 8 + 0];
            ulonglong2 a23 = *(const ulonglong2*)&As2[p][k][ty * 8 + 2];
            ulonglong2 a45 = *(const ulonglong2*)&As2[p][k][ty * 8 + 4];
            ulonglong2 a67 = *(const ulonglong2*)&As2[p][k][ty * 8 + 6];
            ulonglong2 b01 = *(const ulonglong2*)&Bs[p][k][tx * 8];
            ulonglong2 b23 = *(const ulonglong2*)&Bs[p][k][tx * 8 + 4];
            u64 ad[8] = {a01.x, a01.y, a23.x, a23.y, a45.x, a45.y, a67.x, a67.y};
#pragma unroll
            for (int i = 0; i < 8; i++) {
                fma2(acc[i][0], ad[i], b01.x);
                fma2(acc[i][1], ad[i], b01.y);
                fma2(acc[i][2], ad[i], b23.x);
                fma2(acc[i][3], ad[i], b23.y);
            }
        }
        if (it < 31) {
            const int np = p ^ 1;
            As2[np][acol + 0][arow] = make_float2(av.x, av.x);
            As2[np][acol + 1][arow] = make_float2(av.y, av.y);
            As2[np][acol + 2][arow] = make_float2(av.z, av.z);
            As2[np][acol + 3][arow] = make_float2(av.w, av.w);
            *(float4*)&Bs[np][brow][bcol] = bv;
        }
        __syncthreads();
    }

    float bb[8];
#pragma unroll
    for (int j = 0; j < 8; j++) bb[j] = bias[nb + tx * 8 + j];

#pragma unroll
    for (int i = 0; i < 8; i++) {
        size_t m = (size_t)bm * 128 + ty * 8 + i;
        float* op = &g_xfh[m * 512 + (size_t)bn * 128 + tx * 8];
        float2 c0 = u2f(acc[i][0]), c1 = u2f(acc[i][1]);
        float2 c2 = u2f(acc[i][2]), c3 = u2f(acc[i][3]);
        float4 v0, v1;
        v0.x = c0.x + bb[0]; v0.y = c0.y + bb[1];
        v0.z = c1.x + bb[2]; v0.w = c1.y + bb[3];
        v1.x = c2.x + bb[4]; v1.y = c2.y + bb[5];
        v1.z = c3.x + bb[6]; v1.w = c3.y + bb[7];
        *(float4*)&op[0] = v0;
        *(float4*)&op[4] = v1;
    }
}

// ---------------- persistent recurrence: 32 groups x 2 batches ---------------
// Same per-source mbarrier protocol + st.async transport as R11. U natural
// (c0,c1) register pairs; h arrives sender-duplicated: sHp[buf][k] =
// (h0,h0,h1,h1). Occupancy 2 CTAs/SM -> 256 CTAs cover the recurrence.
__global__ __launch_bounds__(256, 2) __cluster_dims__(CPG, 1, 1)
void rec_kernel(const float* __restrict__ Uf, const float* __restrict__ Uh,
                const float* __restrict__ pa, float* __restrict__ out)
{
    __shared__ float4 sHp[2][256];                     // 8 KB recv: [buf][k]=(h0,h0,h1,h1)
    __shared__ float  sRed[64 * 17];                   // 4.4 KB: [vc][b*8+w]
    __shared__ __align__(16) float sOut[2][128];       // 1 KB staging: [buf][col*4+b*2+d]
    __shared__ __align__(16) u64 mbar[2][CPG];         // per-buffer, per-source

    const int g   = blockIdx.x >> 3;                   // 0..31
    unsigned cgi;
    asm("mov.u32 %0, %%cluster_ctarank;" : "=r"(cgi));
    const int j0  = (int)cgi * 32;
    const int tid = threadIdx.x;
    const int w   = tid >> 5;
    const int l   = tid & 31;
    const int kb  = w * 32;
    const int vc0 = 2 * l;

    // Register-resident U as NATURAL (c0,c1) pairs: 32 x u64 per thread.
    const float* __restrict__ Usrc = (vc0 < 32) ? Uf : Uh;
    const int c0 = j0 + (vc0 & 31);
    u64 uu[32];
#pragma unroll
    for (int i = 0; i < 32; i++)
        uu[i] = *(const u64*)&Usrc[(size_t)(kb + i) * H_SZ + c0];
    const float aP = pa[0];

    const unsigned sH_a = smem_u32(&sHp[0][0]);
    const unsigned mb_a = smem_u32(&mbar[0][0]);

    // Zero buffer 0 (step-0 h = 0); init barriers; pre-post expects for buf 1.
    sHp[0][tid] = make_float4(0.f, 0.f, 0.f, 0.f);
    if (tid == 0) {
#pragma unroll
        for (int s = 0; s < 2 * CPG; s++)
            asm volatile("mbarrier.init.shared.b64 [%0], 1;"
                         :: "r"(mb_a + 8u * s) : "memory");
#pragma unroll
        for (int s = 0; s < CPG; s++)   // buffer 1 first fill (sent at end of t=0)
            asm volatile("mbarrier.arrive.expect_tx.shared.b64 _, [%0], %1;"
                         :: "r"(mb_a + 8u * (CPG + s)), "r"(512u) : "memory");
    }
    __syncthreads();
    asm volatile("barrier.cluster.arrive.aligned;" ::: "memory");
    asm volatile("barrier.cluster.wait.aligned;" ::: "memory");

    // All-rank remote addresses, staggered start (r -> rank (cgi+r)&7).
    unsigned rbase[CPG], rmb[CPG];
#pragma unroll
    for (int r = 0; r < CPG; r++) {
        const unsigned rr = (cgi + (unsigned)r) & 7u;
        asm("mapa.shared::cluster.u32 %0, %1, %2;" : "=r"(rbase[r]) : "r"(sH_a), "r"(rr));
        asm("mapa.shared::cluster.u32 %0, %1, %2;" : "=r"(rmb[r])  : "r"(mb_a), "r"(rr));
    }

    const int ecol = tid & 31;
    const int eb   = tid >> 5;                // batch (valid for tid < 64)

    // Deep prefetch: xf/xh for step t are loaded at the top of step t-1.
    const size_t xstride = (size_t)B_SZ * 512;
    const size_t xbase0  = ((size_t)(g * NB + eb)) * 512 + j0 + ecol;
    float xfv = 0.f, xhv = 0.f;
    if (tid < 64) {
        xfv = g_xfh[xbase0];          // t = 0
        xhv = g_xfh[xbase0 + 256];
    }

    int par[2] = {0, 0};

    for (int t = 0; t < T_LEN; t++) {
        const int b = t & 1;

        // Issue NEXT step's xf/xh loads now (~full step of latency cover).
        float xfn = 0.f, xhn = 0.f;
        if (tid < 64) {
            const size_t tt = (t + 1 < T_LEN) ? (size_t)(t + 1) : (size_t)t;
            xfn = g_xfh[tt * xstride + xbase0];
            xhn = g_xfh[tt * xstride + xbase0 + 256];
        }

        if (t > 0) {   // warp w waits ONLY for its own source chunk
            const unsigned mb = mb_a + 8u * (unsigned)(b * CPG + w);
            asm volatile(
                "{\n\t .reg .pred p;\n\t"
                "LW%=:\n\t"
                "mbarrier.try_wait.parity.acquire.cluster.shared::cta.b64 p, [%0], %1, 0x989680;\n\t"
                "@!p bra LW%=;\n\t}"
                :: "r"(mb), "r"((unsigned)par[b]) : "memory");
            par[b] ^= 1;
        }

        const float4* __restrict__ hR = &sHp[b][0];

        u64 a0 = 0ull, a1 = 0ull;   // (c0,c1) partials for batch 0 / batch 1
#pragma unroll
        for (int i = 0; i < 32; i++) {
            ulonglong2 hp = *(const ulonglong2*)&hR[kb + i];  // (h0,h0),(h1,h1)
            fma2(a0, uu[i], hp.x);
            fma2(a1, uu[i], hp.y);
        }
        {
            float2 p0 = u2f(a0), p1 = u2f(a1);
            float* r0 = &sRed[vc0 * 17 + w];
            float* r1 = &sRed[(vc0 + 1) * 17 + w];
            r0[0] = p0.x;  r1[0] = p0.y;
            r0[8] = p1.x;  r1[8] = p1.y;
        }
        __syncthreads();   // partials visible; all source chunks now arrived

        // Post expects for buffer b's NEXT fill before our sends (ordered by
        // the pre-send sync below). Skip last two steps -> barriers end clean.
        if (tid < 8 && t < T_LEN - 2)
            asm volatile("mbarrier.arrive.expect_tx.shared.b64 _, [%0], %1;"
                         :: "r"(mb_a + 8u * (unsigned)(b * CPG + tid)), "r"(512u)
                         : "memory");

        const int sb = (t + 1) & 1;   // staging/send buffer
        float hv = 0.0f;
        if (tid < 64) {
            const float* rf = &sRed[ecol * 17 + eb * 8];
            const float* rh = &sRed[(ecol + 32) * 17 + eb * 8];
            float pf = ((rf[0] + rf[1]) + (rf[2] + rf[3]))
                     + ((rf[4] + rf[5]) + (rf[6] + rf[7])) + xfv;
            float ph = ((rh[0] + rh[1]) + (rh[2] + rh[3]))
                     + ((rh[4] + rh[5]) + (rh[6] + rh[7])) + xhv;

            float f  = fast_sigmoid(pf);
            float hn = fast_tanh(ph);
            float ho = ((const float*)&hR[j0 + ecol])[eb * 2];
            hv = f * ho + (1.0f - f) * hn;
            hv = (hv >= 0.0f) ? hv : aP * hv;

            // Duplicated staging: (h, h) at [col*4 + b*2 .. +1].
            sOut[sb][ecol * 4 + eb * 2]     = hv;
            sOut[sb][ecol * 4 + eb * 2 + 1] = hv;
        }
        __syncthreads();   // staging + expect posts visible before sends

        if (t < T_LEN - 1 && tid < 32) {
            // Lane l owns float4 #l (16 B = col l's (h0,h0,h1,h1)); one
            // st.async.v2.b64 warp-instruction per destination rank.
            ulonglong2 pay = *(const ulonglong2*)&sOut[sb][tid * 4];
            const unsigned doff = (unsigned)sb * 4096u + cgi * 512u
                                + (unsigned)tid * 16u;
            const unsigned mbo  = 8u * ((unsigned)sb * CPG + cgi);
#pragma unroll
            for (int r = 0; r < CPG; r++) {
                asm volatile(
                    "st.async.shared::cluster.mbarrier::complete_tx::bytes.v2.b64 "
                    "[%0], {%1, %2}, [%3];"
                    :: "r"(rbase[r] + doff), "l"(pay.x), "l"(pay.y),
                       "r"(rmb[r] + mbo)
                    : "memory");
            }
        }
        // Global store off the critical path (after send issue).
        if (tid < 64)
            out[((size_t)t * B_SZ + g * NB + eb) * H_SZ + j0 + ecol] = hv;

        xfv = xfn;
        xhv = xhn;
    }

    asm volatile("barrier.cluster.arrive.aligned;" ::: "memory");
    asm volatile("barrier.cluster.wait.aligned;" ::: "memory");
    if (tid == 0) {   // leave raw memory for next graph replay's init
#pragma unroll
        for (int s = 0; s < 2 * CPG; s++)
            asm volatile("mbarrier.inval.shared.b64 [%0];"
                         :: "r"(mb_a + 8u * s) : "memory");
    }
}

// ---------------- launch ------------------------------------------------------
extern "C" void kernel_launch(void* const* d_in, const int* in_sizes, int n_in,
                              void* d_out, int out_size) {
    (void)in_sizes; (void)n_in; (void)out_size;
    const float* seq = (const float*)d_in[0];
    const float* Wf  = (const float*)d_in[1];
    const float* Uf  = (const float*)d_in[2];
    const float* bf  = (const float*)d_in[3];
    const float* Wh  = (const float*)d_in[4];
    const float* Uh  = (const float*)d_in[5];
    const float* bh  = (const float*)d_in[6];
    const float* pa  = (const float*)d_in[7];
    float* out = (float*)d_out;

    dim3 pgrid(T_LEN * B_SZ / 128, 4);
    proj_kernel<<<pgrid, 256>>>(seq, Wf, bf, Wh, bh);

    rec_kernel<<<NGRP * CPG, 256>>>(Uf, Uh, pa, out);
}